// round 2
// baseline (speedup 1.0000x reference)
#include <cuda_runtime.h>

// MultiHeadAttention: B=4096, T=128, C=128, H=4, D=32, causal, scale = C^-0.5
// One CTA per batch element, 256 threads, fp32 with packed f32x2 FMA (FFMA2).

#define NB 4096
#define TT 128
#define CC 128
#define HH 4
#define DD 32
#define SCALE 0.08838834764831845f   // 1/sqrt(128)

// shared memory layout (float offsets)
#define OFF_XST 0         // xst[c][t]   [128][132]
#define OFF_QT  16896     // qt[d][t]    [32][132]
#define OFF_KT  21120     // kt[d][s]    [32][132]
#define OFF_VV  25344     // vv[s][d]    [128][36]
#define OFF_WUN 29952     // union: w3[3][128][36] (13824) / pt[s][t] [128][132] (16896)
#define OFF_OT  46848     // ot[d][t]    [32][132]
#define OFF_WPT 51072     // wpt[d][c]   [32][132]
#define OFF_BPS 55296     // bps[128]
#define SMEM_FLOATS 55424

typedef unsigned long long u64t;

__device__ __forceinline__ u64t fma2(u64t a, u64t b, u64t c) {
    u64t d;
    asm("fma.rn.f32x2 %0, %1, %2, %3;" : "=l"(d) : "l"(a), "l"(b), "l"(c));
    return d;
}
__device__ __forceinline__ u64t splat2(float x) {
    u64t r;
    asm("mov.b64 %0, {%1, %2};" : "=l"(r) : "f"(x), "f"(x));
    return r;
}
__device__ __forceinline__ float2 unpack2(u64t v) {
    float2 r;
    asm("mov.b64 {%0, %1}, %2;" : "=f"(r.x), "=f"(r.y) : "l"(v));
    return r;
}

__global__ void __launch_bounds__(256, 1)
mha_f32x2_kernel(const float* __restrict__ x,
                 const float* __restrict__ Wq,
                 const float* __restrict__ Wk,
                 const float* __restrict__ Wv,
                 const float* __restrict__ Wp,
                 const float* __restrict__ bp,
                 float* __restrict__ out)
{
    extern __shared__ float sm[];
    float* xst = sm + OFF_XST;
    float* qt  = sm + OFF_QT;
    float* kt  = sm + OFF_KT;
    float* vv  = sm + OFF_VV;
    float* wun = sm + OFF_WUN;   // W staging, later P (transposed+swizzled)
    float* ot  = sm + OFF_OT;
    float* wpt = sm + OFF_WPT;
    float* bps = sm + OFF_BPS;

    const int tid = threadIdx.x;
    const int b   = blockIdx.x;
    const float* xb = x + (size_t)b * (TT * CC);

    // ---- load x transposed: xst[c][t] = x[t][c] ----
    {
        int t  = tid >> 1;
        int ch = (tid & 1) * 64;
        #pragma unroll
        for (int j = 0; j < 16; ++j) {
            int c = ch + j * 4;
            float4 v = *reinterpret_cast<const float4*>(xb + t * CC + c);
            xst[(c + 0) * 132 + t] = v.x;
            xst[(c + 1) * 132 + t] = v.y;
            xst[(c + 2) * 132 + t] = v.z;
            xst[(c + 3) * 132 + t] = v.w;
        }
        if (tid < 128) bps[tid] = bp[tid];
    }

    // persistent output accumulator: thread (cx,cy) owns 8x8 tile of out[T][C]
    const int cx = tid & 15;         // column group: c0 = cx*8
    const int cy = tid >> 4;         // row group:    t0 = cy*8
    u64t oacc[8][4];
    #pragma unroll
    for (int i = 0; i < 8; ++i)
        #pragma unroll
        for (int j = 0; j < 4; ++j) oacc[i][j] = 0ull;

    // 4x4 tile layout used by G1 (QKV proj) and G3 (PV)
    const int dg = tid & 7;          // d0 = dg*4
    const int rg = tid >> 3;         // r0 = rg*4
    const int d0 = dg * 4;
    const int r0 = rg * 4;

    for (int h = 0; h < HH; ++h) {
        __syncthreads();   // protects wun/wpt reuse across head iterations

        // ---- stage W for this head ----
        {
            #pragma unroll
            for (int m = 0; m < 3; ++m) {
                const float* wsrc = (m == 0) ? (Wq + h * CC * DD)
                                  : (m == 1) ? (Wk + h * CC * DD)
                                             : (Wv + h * CC * DD);
                float* wdst = wun + m * 4608;     // [128][36]
                #pragma unroll
                for (int f = 0; f < CC * DD; f += 1024) {
                    int ff = f + tid * 4;
                    int k = ff >> 5, d = ff & 31;
                    float4 v = *reinterpret_cast<const float4*>(wsrc + ff);
                    *reinterpret_cast<float4*>(wdst + k * 36 + d) = v;
                }
            }
            // wpt[d][c] = Wp[c][h*32+d]
            int c  = tid >> 1;
            int dh = (tid & 1) * 16;
            #pragma unroll
            for (int j = 0; j < 16; j += 4) {
                float4 v = *reinterpret_cast<const float4*>(Wp + c * CC + h * DD + dh + j);
                wpt[(dh + j + 0) * 132 + c] = v.x;
                wpt[(dh + j + 1) * 132 + c] = v.y;
                wpt[(dh + j + 2) * 132 + c] = v.z;
                wpt[(dh + j + 3) * 132 + c] = v.w;
            }
        }
        __syncthreads();

        // ---- G1: Q/K/V = x @ W  (out [128][32], 4x4 tiles, k=128) ----
        {
            #pragma unroll
            for (int m = 0; m < 3; ++m) {
                const float* w = wun + m * 4608;
                u64t acc[4][2];
                #pragma unroll
                for (int i = 0; i < 4; ++i) { acc[i][0] = 0ull; acc[i][1] = 0ull; }
                #pragma unroll 4
                for (int k = 0; k < CC; ++k) {
                    float4 a = *reinterpret_cast<const float4*>(xst + k * 132 + r0);
                    const u64t* wb = reinterpret_cast<const u64t*>(w + k * 36 + d0);
                    u64t b01 = wb[0], b23 = wb[1];
                    u64t a0 = splat2(a.x), a1 = splat2(a.y), a2 = splat2(a.z), a3 = splat2(a.w);
                    acc[0][0] = fma2(a0, b01, acc[0][0]); acc[0][1] = fma2(a0, b23, acc[0][1]);
                    acc[1][0] = fma2(a1, b01, acc[1][0]); acc[1][1] = fma2(a1, b23, acc[1][1]);
                    acc[2][0] = fma2(a2, b01, acc[2][0]); acc[2][1] = fma2(a2, b23, acc[2][1]);
                    acc[3][0] = fma2(a3, b01, acc[3][0]); acc[3][1] = fma2(a3, b23, acc[3][1]);
                }
                #pragma unroll
                for (int i = 0; i < 4; ++i) {
                    #pragma unroll
                    for (int jp = 0; jp < 2; ++jp) {
                        if (m == 2) {
                            *reinterpret_cast<u64t*>(vv + (r0 + i) * 36 + d0 + 2 * jp) = acc[i][jp];
                        } else {
                            float2 v = unpack2(acc[i][jp]);
                            float* dst = (m == 0) ? qt : kt;
                            dst[(d0 + 2 * jp) * 132 + r0 + i]     = v.x;
                            dst[(d0 + 2 * jp + 1) * 132 + r0 + i] = v.y;
                        }
                    }
                }
            }
        }
        __syncthreads();

        // ---- G2: S = Q K^T, causal softmax -> pt (8x8 tiles, k=32) ----
        {
            const int sr0 = cy * 8;    // score rows
            const int ss0 = cx * 8;    // score cols
            u64t sacc[8][4];
            #pragma unroll
            for (int i = 0; i < 8; ++i)
                #pragma unroll
                for (int j = 0; j < 4; ++j) sacc[i][j] = 0ull;

            #pragma unroll 4
            for (int d = 0; d < DD; ++d) {
                const float* qrow = qt + d * 132;
                const float* krow = kt + d * 132;
                float4 a0 = *reinterpret_cast<const float4*>(qrow + sr0);
                float4 a1 = *reinterpret_cast<const float4*>(qrow + sr0 + 4);
                const u64t* kb = reinterpret_cast<const u64t*>(krow + ss0);
                u64t b0 = kb[0], b1 = kb[1], b2 = kb[2], b3 = kb[3];
                float ar[8] = {a0.x, a0.y, a0.z, a0.w, a1.x, a1.y, a1.z, a1.w};
                #pragma unroll
                for (int i = 0; i < 8; ++i) {
                    u64t ap = splat2(ar[i]);
                    sacc[i][0] = fma2(ap, b0, sacc[i][0]);
                    sacc[i][1] = fma2(ap, b1, sacc[i][1]);
                    sacc[i][2] = fma2(ap, b2, sacc[i][2]);
                    sacc[i][3] = fma2(ap, b3, sacc[i][3]);
                }
            }

            float p[8][8];
            #pragma unroll
            for (int i = 0; i < 8; ++i) {
                int r = sr0 + i;
                #pragma unroll
                for (int jp = 0; jp < 4; ++jp) {
                    float2 v = unpack2(sacc[i][jp]);
                    int s = ss0 + 2 * jp;
                    p[i][2 * jp]     = (s     <= r) ? v.x * SCALE : -3.0e38f;
                    p[i][2 * jp + 1] = (s + 1 <= r) ? v.y * SCALE : -3.0e38f;
                }
            }
            // row softmax: reduce across the 16 cx lanes (lane bits 0..3)
            #pragma unroll
            for (int i = 0; i < 8; ++i) {
                float m = p[i][0];
                #pragma unroll
                for (int j = 1; j < 8; ++j) m = fmaxf(m, p[i][j]);
                #pragma unroll
                for (int o = 1; o < 16; o <<= 1)
                    m = fmaxf(m, __shfl_xor_sync(0xffffffffu, m, o));
                float sum = 0.f;
                #pragma unroll
                for (int j = 0; j < 8; ++j) { float e = __expf(p[i][j] - m); p[i][j] = e; sum += e; }
                #pragma unroll
                for (int o = 1; o < 16; o <<= 1)
                    sum += __shfl_xor_sync(0xffffffffu, sum, o);
                float inv = __frcp_rn(sum);
                #pragma unroll
                for (int j = 0; j < 8; ++j) p[i][j] *= inv;
            }
            // store pt[s][r] with XOR swizzle on r bits 2..4 (kills 16-way conflict)
            #pragma unroll
            for (int j = 0; j < 8; ++j) {
                int s  = ss0 + j;
                int xr = ((s >> 3) & 7) << 2;
                float* prow = wun + s * 132;
                #pragma unroll
                for (int i = 0; i < 8; ++i)
                    prow[(sr0 + i) ^ xr] = p[i][j];
            }
        }
        __syncthreads();

        // ---- G3: O = P @ V  (out [128][32], 4x4 tiles, k=128) ----
        {
            u64t acc[4][2];
            #pragma unroll
            for (int i = 0; i < 4; ++i) { acc[i][0] = 0ull; acc[i][1] = 0ull; }
            #pragma unroll 4
            for (int s = 0; s < TT; ++s) {
                int xr = ((s >> 3) & 7) << 2;
                const float* prow = wun + s * 132;
                float4 a = *reinterpret_cast<const float4*>(prow + (r0 ^ xr));
                const u64t* vb = reinterpret_cast<const u64t*>(vv + s * 36 + d0);
                u64t b0 = vb[0], b1 = vb[1];
                u64t a0 = splat2(a.x), a1 = splat2(a.y), a2 = splat2(a.z), a3 = splat2(a.w);
                acc[0][0] = fma2(a0, b0, acc[0][0]); acc[0][1] = fma2(a0, b1, acc[0][1]);
                acc[1][0] = fma2(a1, b0, acc[1][0]); acc[1][1] = fma2(a1, b1, acc[1][1]);
                acc[2][0] = fma2(a2, b0, acc[2][0]); acc[2][1] = fma2(a2, b1, acc[2][1]);
                acc[3][0] = fma2(a3, b0, acc[3][0]); acc[3][1] = fma2(a3, b1, acc[3][1]);
            }
            // store transposed: ot[d][t]
            #pragma unroll
            for (int i = 0; i < 4; ++i) {
                #pragma unroll
                for (int jp = 0; jp < 2; ++jp) {
                    float2 v = unpack2(acc[i][jp]);
                    ot[(d0 + 2 * jp) * 132 + r0 + i]     = v.x;
                    ot[(d0 + 2 * jp + 1) * 132 + r0 + i] = v.y;
                }
            }
        }
        __syncthreads();

        // ---- G4: out_acc += O @ Wp_h^T  (8x8 tiles, k=32, register-resident) ----
        {
            const int t0 = cy * 8;
            const int c0 = cx * 8;
            #pragma unroll 4
            for (int d = 0; d < DD; ++d) {
                const float* orow = ot + d * 132;
                const float* wrow = wpt + d * 132;
                float4 a0 = *reinterpret_cast<const float4*>(orow + t0);
                float4 a1 = *reinterpret_cast<const float4*>(orow + t0 + 4);
                const u64t* wb = reinterpret_cast<const u64t*>(wrow + c0);
                u64t b0 = wb[0], b1 = wb[1], b2 = wb[2], b3 = wb[3];
                float ar[8] = {a0.x, a0.y, a0.z, a0.w, a1.x, a1.y, a1.z, a1.w};
                #pragma unroll
                for (int i = 0; i < 8; ++i) {
                    u64t ap = splat2(ar[i]);
                    oacc[i][0] = fma2(ap, b0, oacc[i][0]);
                    oacc[i][1] = fma2(ap, b1, oacc[i][1]);
                    oacc[i][2] = fma2(ap, b2, oacc[i][2]);
                    oacc[i][3] = fma2(ap, b3, oacc[i][3]);
                }
            }
        }
    }

    // ---- epilogue: out = acc + bp ----
    {
        const int t0 = cy * 8;
        const int c0 = cx * 8;
        float bv[8];
        #pragma unroll
        for (int j = 0; j < 8; ++j) bv[j] = bps[c0 + j];
        #pragma unroll
        for (int i = 0; i < 8; ++i) {
            float2 p0 = unpack2(oacc[i][0]);
            float2 p1 = unpack2(oacc[i][1]);
            float2 p2 = unpack2(oacc[i][2]);
            float2 p3 = unpack2(oacc[i][3]);
            float4 v0 = make_float4(p0.x + bv[0], p0.y + bv[1], p1.x + bv[2], p1.y + bv[3]);
            float4 v1 = make_float4(p2.x + bv[4], p2.y + bv[5], p3.x + bv[6], p3.y + bv[7]);
            size_t base = ((size_t)b * TT + (t0 + i)) * CC + c0;
            *reinterpret_cast<float4*>(out + base)     = v0;
            *reinterpret_cast<float4*>(out + base + 4) = v1;
        }
    }
}

extern "C" void kernel_launch(void* const* d_in, const int* in_sizes, int n_in,
                              void* d_out, int out_size)
{
    (void)in_sizes; (void)n_in; (void)out_size;
    const float* x  = (const float*)d_in[0];
    const float* Wq = (const float*)d_in[1];
    const float* Wk = (const float*)d_in[2];
    const float* Wv = (const float*)d_in[3];
    const float* Wp = (const float*)d_in[4];
    const float* bp = (const float*)d_in[5];
    float* out = (float*)d_out;

    const int smem_bytes = SMEM_FLOATS * 4;   // 221,696 B
    cudaFuncSetAttribute(mha_f32x2_kernel,
                         cudaFuncAttributeMaxDynamicSharedMemorySize, smem_bytes);
    mha_f32x2_kernel<<<NB, 256, smem_bytes>>>(x, Wq, Wk, Wv, Wp, bp, out);
}

// round 3
// speedup vs baseline: 1.1231x; 1.1231x over previous
#include <cuda_runtime.h>

// MultiHeadAttention: B=4096, T=128, C=128, H=4, D=32, causal, scale = C^-0.5
// One CTA per batch element, 256 threads, fp32 with packed f32x2 FMA (FFMA2).
// R3: fused QKV mainloop (shared A), causal skip in G2 (lane-predicated) and G3 (loop bound).

#define NB 4096
#define TT 128
#define CC 128
#define HH 4
#define DD 32
#define SCALE 0.08838834764831845f   // 1/sqrt(128)

// shared memory layout (float offsets)
#define OFF_XST 0         // xst[c][t]   [128][132]
#define OFF_QT  16896     // qt[d][t]    [32][132]
#define OFF_KT  21120     // kt[d][s]    [32][132]
#define OFF_VV  25344     // vv[s][d]    [128][36]
#define OFF_WUN 29952     // union: w3[3][128][36] (13824) / pt[s][t] [128][132] (16896)
#define OFF_OT  46848     // ot[d][t]    [32][132]
#define OFF_WPT 51072     // wpt[d][c]   [32][132]
#define OFF_BPS 55296     // bps[128]
#define SMEM_FLOATS 55424

typedef unsigned long long u64t;

__device__ __forceinline__ u64t fma2(u64t a, u64t b, u64t c) {
    u64t d;
    asm("fma.rn.f32x2 %0, %1, %2, %3;" : "=l"(d) : "l"(a), "l"(b), "l"(c));
    return d;
}
__device__ __forceinline__ u64t splat2(float x) {
    u64t r;
    asm("mov.b64 %0, {%1, %2};" : "=l"(r) : "f"(x), "f"(x));
    return r;
}
__device__ __forceinline__ float2 unpack2(u64t v) {
    float2 r;
    asm("mov.b64 {%0, %1}, %2;" : "=f"(r.x), "=f"(r.y) : "l"(v));
    return r;
}

__global__ void __launch_bounds__(256, 1)
mha_f32x2_kernel(const float* __restrict__ x,
                 const float* __restrict__ Wq,
                 const float* __restrict__ Wk,
                 const float* __restrict__ Wv,
                 const float* __restrict__ Wp,
                 const float* __restrict__ bp,
                 float* __restrict__ out)
{
    extern __shared__ float sm[];
    float* xst = sm + OFF_XST;
    float* qt  = sm + OFF_QT;
    float* kt  = sm + OFF_KT;
    float* vv  = sm + OFF_VV;
    float* wun = sm + OFF_WUN;   // W staging, later P (transposed+swizzled)
    float* ot  = sm + OFF_OT;
    float* wpt = sm + OFF_WPT;
    float* bps = sm + OFF_BPS;

    const int tid = threadIdx.x;
    const int b   = blockIdx.x;
    const float* xb = x + (size_t)b * (TT * CC);

    // ---- load x transposed: xst[c][t] = x[t][c] ----
    {
        int t  = tid >> 1;
        int ch = (tid & 1) * 64;
        #pragma unroll
        for (int j = 0; j < 16; ++j) {
            int c = ch + j * 4;
            float4 v = *reinterpret_cast<const float4*>(xb + t * CC + c);
            xst[(c + 0) * 132 + t] = v.x;
            xst[(c + 1) * 132 + t] = v.y;
            xst[(c + 2) * 132 + t] = v.z;
            xst[(c + 3) * 132 + t] = v.w;
        }
        if (tid < 128) bps[tid] = bp[tid];
    }

    // persistent output accumulator: thread (cx,cy) owns 8x8 tile of out[T][C]
    const int cx = tid & 15;         // column group: c0 = cx*8
    const int cy = tid >> 4;         // row group:    t0 = cy*8
    u64t oacc[8][4];
    #pragma unroll
    for (int i = 0; i < 8; ++i)
        #pragma unroll
        for (int j = 0; j < 4; ++j) oacc[i][j] = 0ull;

    // 4x4 tile layout used by G1 (QKV proj) and G3 (PV)
    const int dg = tid & 7;          // d0 = dg*4
    const int rg = tid >> 3;         // r0 = rg*4
    const int d0 = dg * 4;
    const int r0 = rg * 4;

    for (int h = 0; h < HH; ++h) {
        __syncthreads();   // protects wun/wpt reuse across head iterations

        // ---- stage W for this head ----
        {
            #pragma unroll
            for (int m = 0; m < 3; ++m) {
                const float* wsrc = (m == 0) ? (Wq + h * CC * DD)
                                  : (m == 1) ? (Wk + h * CC * DD)
                                             : (Wv + h * CC * DD);
                float* wdst = wun + m * 4608;     // [128][36]
                #pragma unroll
                for (int f = 0; f < CC * DD; f += 1024) {
                    int ff = f + tid * 4;
                    int k = ff >> 5, d = ff & 31;
                    float4 v = *reinterpret_cast<const float4*>(wsrc + ff);
                    *reinterpret_cast<float4*>(wdst + k * 36 + d) = v;
                }
            }
            // wpt[d][c] = Wp[c][h*32+d]
            int c  = tid >> 1;
            int dh = (tid & 1) * 16;
            #pragma unroll
            for (int j = 0; j < 16; j += 4) {
                float4 v = *reinterpret_cast<const float4*>(Wp + c * CC + h * DD + dh + j);
                wpt[(dh + j + 0) * 132 + c] = v.x;
                wpt[(dh + j + 1) * 132 + c] = v.y;
                wpt[(dh + j + 2) * 132 + c] = v.z;
                wpt[(dh + j + 3) * 132 + c] = v.w;
            }
        }
        __syncthreads();

        // ---- G1 (fused): Q,K,V = x @ {Wq,Wk,Wv}  — one A load feeds 3 B's ----
        {
            u64t acc[3][4][2];
            #pragma unroll
            for (int m = 0; m < 3; ++m)
                #pragma unroll
                for (int i = 0; i < 4; ++i) { acc[m][i][0] = 0ull; acc[m][i][1] = 0ull; }

            #pragma unroll 2
            for (int k = 0; k < CC; ++k) {
                float4 a = *reinterpret_cast<const float4*>(xst + k * 132 + r0);
                u64t a0 = splat2(a.x), a1 = splat2(a.y), a2 = splat2(a.z), a3 = splat2(a.w);
                #pragma unroll
                for (int m = 0; m < 3; ++m) {
                    const u64t* wb = reinterpret_cast<const u64t*>(wun + m * 4608 + k * 36 + d0);
                    u64t b01 = wb[0], b23 = wb[1];
                    acc[m][0][0] = fma2(a0, b01, acc[m][0][0]); acc[m][0][1] = fma2(a0, b23, acc[m][0][1]);
                    acc[m][1][0] = fma2(a1, b01, acc[m][1][0]); acc[m][1][1] = fma2(a1, b23, acc[m][1][1]);
                    acc[m][2][0] = fma2(a2, b01, acc[m][2][0]); acc[m][2][1] = fma2(a2, b23, acc[m][2][1]);
                    acc[m][3][0] = fma2(a3, b01, acc[m][3][0]); acc[m][3][1] = fma2(a3, b23, acc[m][3][1]);
                }
            }
            // epilogues: Q,K transposed; V natural (u64 stores)
            #pragma unroll
            for (int i = 0; i < 4; ++i) {
                #pragma unroll
                for (int jp = 0; jp < 2; ++jp) {
                    float2 vq = unpack2(acc[0][i][jp]);
                    qt[(d0 + 2 * jp) * 132 + r0 + i]     = vq.x;
                    qt[(d0 + 2 * jp + 1) * 132 + r0 + i] = vq.y;
                    float2 vk = unpack2(acc[1][i][jp]);
                    kt[(d0 + 2 * jp) * 132 + r0 + i]     = vk.x;
                    kt[(d0 + 2 * jp + 1) * 132 + r0 + i] = vk.y;
                    *reinterpret_cast<u64t*>(vv + (r0 + i) * 36 + d0 + 2 * jp) = acc[2][i][jp];
                }
            }
        }
        __syncthreads();

        // ---- G2: S = Q K^T, causal softmax -> pt (8x8 tiles, k=32) ----
        {
            const int sr0 = cy * 8;    // score rows
            const int ss0 = cx * 8;    // score cols
            const bool live = (cx <= cy);   // tile touches the causal triangle

            float p[8][8];
            if (live) {
                u64t sacc[8][4];
                #pragma unroll
                for (int i = 0; i < 8; ++i)
                    #pragma unroll
                    for (int j = 0; j < 4; ++j) sacc[i][j] = 0ull;

                #pragma unroll 4
                for (int d = 0; d < DD; ++d) {
                    const float* qrow = qt + d * 132;
                    const float* krow = kt + d * 132;
                    float4 a0 = *reinterpret_cast<const float4*>(qrow + sr0);
                    float4 a1 = *reinterpret_cast<const float4*>(qrow + sr0 + 4);
                    const u64t* kb = reinterpret_cast<const u64t*>(krow + ss0);
                    u64t b0 = kb[0], b1 = kb[1], b2 = kb[2], b3 = kb[3];
                    float ar[8] = {a0.x, a0.y, a0.z, a0.w, a1.x, a1.y, a1.z, a1.w};
                    #pragma unroll
                    for (int i = 0; i < 8; ++i) {
                        u64t ap = splat2(ar[i]);
                        sacc[i][0] = fma2(ap, b0, sacc[i][0]);
                        sacc[i][1] = fma2(ap, b1, sacc[i][1]);
                        sacc[i][2] = fma2(ap, b2, sacc[i][2]);
                        sacc[i][3] = fma2(ap, b3, sacc[i][3]);
                    }
                }
                #pragma unroll
                for (int i = 0; i < 8; ++i) {
                    int r = sr0 + i;
                    #pragma unroll
                    for (int jp = 0; jp < 4; ++jp) {
                        float2 v = unpack2(sacc[i][jp]);
                        int s = ss0 + 2 * jp;
                        p[i][2 * jp]     = (s     <= r) ? v.x * SCALE : -3.0e38f;
                        p[i][2 * jp + 1] = (s + 1 <= r) ? v.y * SCALE : -3.0e38f;
                    }
                }
            } else {
                #pragma unroll
                for (int i = 0; i < 8; ++i)
                    #pragma unroll
                    for (int j = 0; j < 8; ++j) p[i][j] = -3.0e38f;
            }

            // row softmax: reduce across the 16 cx lanes (lane bits 0..3); all lanes join
            #pragma unroll
            for (int i = 0; i < 8; ++i) {
                float m = p[i][0];
                #pragma unroll
                for (int j = 1; j < 8; ++j) m = fmaxf(m, p[i][j]);
                #pragma unroll
                for (int o = 1; o < 16; o <<= 1)
                    m = fmaxf(m, __shfl_xor_sync(0xffffffffu, m, o));
                float sum = 0.f;
                #pragma unroll
                for (int j = 0; j < 8; ++j) { float e = __expf(p[i][j] - m); p[i][j] = e; sum += e; }
                #pragma unroll
                for (int o = 1; o < 16; o <<= 1)
                    sum += __shfl_xor_sync(0xffffffffu, sum, o);
                float inv = __frcp_rn(sum);
                #pragma unroll
                for (int j = 0; j < 8; ++j) p[i][j] *= inv;
            }

            // store pt[s][r] with XOR swizzle on r bits 2..4 (kills 16-way conflict)
            // skipped tiles (cx>cy) are provably never read by G3 (it reads only s<=t)
            if (live) {
                #pragma unroll
                for (int j = 0; j < 8; ++j) {
                    int s  = ss0 + j;
                    int xr = ((s >> 3) & 7) << 2;
                    float* prow = wun + s * 132;
                    #pragma unroll
                    for (int i = 0; i < 8; ++i)
                        prow[(sr0 + i) ^ xr] = p[i][j];
                }
            }
        }
        __syncthreads();

        // ---- G3: O = P @ V  (4x4 tiles, causal bound: P[t][s]=0 for s>t) ----
        {
            u64t acc[4][2];
            #pragma unroll
            for (int i = 0; i < 4; ++i) { acc[i][0] = 0ull; acc[i][1] = 0ull; }
            const int send = r0 + 4;   // rows r0..r0+3 only need s <= r0+3
            #pragma unroll 4
            for (int s = 0; s < send; ++s) {
                int xr = ((s >> 3) & 7) << 2;
                const float* prow = wun + s * 132;
                float4 a = *reinterpret_cast<const float4*>(prow + (r0 ^ xr));
                const u64t* vb = reinterpret_cast<const u64t*>(vv + s * 36 + d0);
                u64t b0 = vb[0], b1 = vb[1];
                u64t a0 = splat2(a.x), a1 = splat2(a.y), a2 = splat2(a.z), a3 = splat2(a.w);
                acc[0][0] = fma2(a0, b0, acc[0][0]); acc[0][1] = fma2(a0, b1, acc[0][1]);
                acc[1][0] = fma2(a1, b0, acc[1][0]); acc[1][1] = fma2(a1, b1, acc[1][1]);
                acc[2][0] = fma2(a2, b0, acc[2][0]); acc[2][1] = fma2(a2, b1, acc[2][1]);
                acc[3][0] = fma2(a3, b0, acc[3][0]); acc[3][1] = fma2(a3, b1, acc[3][1]);
            }
            // store transposed: ot[d][t]
            #pragma unroll
            for (int i = 0; i < 4; ++i) {
                #pragma unroll
                for (int jp = 0; jp < 2; ++jp) {
                    float2 v = unpack2(acc[i][jp]);
                    ot[(d0 + 2 * jp) * 132 + r0 + i]     = v.x;
                    ot[(d0 + 2 * jp + 1) * 132 + r0 + i] = v.y;
                }
            }
        }
        __syncthreads();

        // ---- G4: out_acc += O @ Wp_h^T  (8x8 tiles, k=32, register-resident) ----
        {
            const int t0 = cy * 8;
            const int c0 = cx * 8;
            #pragma unroll 4
            for (int d = 0; d < DD; ++d) {
                const float* orow = ot + d * 132;
                const float* wrow = wpt + d * 132;
                float4 a0 = *reinterpret_cast<const float4*>(orow + t0);
                float4 a1 = *reinterpret_cast<const float4*>(orow + t0 + 4);
                const u64t* wb = reinterpret_cast<const u64t*>(wrow + c0);
                u64t b0 = wb[0], b1 = wb[1], b2 = wb[2], b3 = wb[3];
                float ar[8] = {a0.x, a0.y, a0.z, a0.w, a1.x, a1.y, a1.z, a1.w};
                #pragma unroll
                for (int i = 0; i < 8; ++i) {
                    u64t ap = splat2(ar[i]);
                    oacc[i][0] = fma2(ap, b0, oacc[i][0]);
                    oacc[i][1] = fma2(ap, b1, oacc[i][1]);
                    oacc[i][2] = fma2(ap, b2, oacc[i][2]);
                    oacc[i][3] = fma2(ap, b3, oacc[i][3]);
                }
            }
        }
    }

    // ---- epilogue: out = acc + bp ----
    {
        const int t0 = cy * 8;
        const int c0 = cx * 8;
        float bv[8];
        #pragma unroll
        for (int j = 0; j < 8; ++j) bv[j] = bps[c0 + j];
        #pragma unroll
        for (int i = 0; i < 8; ++i) {
            float2 p0 = unpack2(oacc[i][0]);
            float2 p1 = unpack2(oacc[i][1]);
            float2 p2 = unpack2(oacc[i][2]);
            float2 p3 = unpack2(oacc[i][3]);
            float4 v0 = make_float4(p0.x + bv[0], p0.y + bv[1], p1.x + bv[2], p1.y + bv[3]);
            float4 v1 = make_float4(p2.x + bv[4], p2.y + bv[5], p3.x + bv[6], p3.y + bv[7]);
            size_t base = ((size_t)b * TT + (t0 + i)) * CC + c0;
            *reinterpret_cast<float4*>(out + base)     = v0;
            *reinterpret_cast<float4*>(out + base + 4) = v1;
        }
    }
}

extern "C" void kernel_launch(void* const* d_in, const int* in_sizes, int n_in,
                              void* d_out, int out_size)
{
    (void)in_sizes; (void)n_in; (void)out_size;
    const float* x  = (const float*)d_in[0];
    const float* Wq = (const float*)d_in[1];
    const float* Wk = (const float*)d_in[2];
    const float* Wv = (const float*)d_in[3];
    const float* Wp = (const float*)d_in[4];
    const float* bp = (const float*)d_in[5];
    float* out = (float*)d_out;

    const int smem_bytes = SMEM_FLOATS * 4;   // 221,696 B
    cudaFuncSetAttribute(mha_f32x2_kernel,
                         cudaFuncAttributeMaxDynamicSharedMemorySize, smem_bytes);
    mha_f32x2_kernel<<<NB, 256, smem_bytes>>>(x, Wq, Wk, Wv, Wp, bp, out);
}